// round 2
// baseline (speedup 1.0000x reference)
#include <cuda_runtime.h>
#include <cuda_bf16.h>
#include <stdint.h>

#define NUM_EXPERTS 8
#define HIDDEN 2048
#define INTER 1408
#define NTOK 8192

#define BM 128
#define BN 64
#define BK 32
#define SL 36              // smem row stride in floats (conflict-free, 16B-aligned)
#define THREADS 256

#define MAX_MTILES (NTOK/BM + NUM_EXPERTS - 1)   // 71
#define NB1 (INTER/BN)     // 22
#define NB2 (HIDDEN/BN)    // 32

#define ASZ (BM*SL)        // 4608 floats per A stage
#define B1SZ (128*SL)      // 4608 floats per B stage (gate 64 rows + up 64 rows)
#define B2SZ (64*SL)       // 2304 floats per B stage (gemm2)
#define SMEM1_BYTES ((2*ASZ + 2*B1SZ)*4)   // 73728
#define SMEM2_BYTES ((2*ASZ + 2*B2SZ)*4)   // 55296

// -------- device scratch --------
__device__ int g_counts[NUM_EXPERTS];
__device__ int g_cursor[NUM_EXPERTS];
__device__ int g_offsets[NUM_EXPERTS + 1];
__device__ int g_mtoff[NUM_EXPERTS + 1];
__device__ int g_perm[NTOK];
__device__ float g_h[(size_t)NTOK * INTER];   // fp32 intermediate, rows in sorted order

// -------- router --------
__global__ void k_reset() {
    int t = threadIdx.x;
    if (t < NUM_EXPERTS) { g_counts[t] = 0; g_cursor[t] = 0; }
}
__global__ void k_count(const int* __restrict__ ids) {
    int i = blockIdx.x * blockDim.x + threadIdx.x;
    if (i < NTOK) atomicAdd(&g_counts[ids[i]], 1);
}
__global__ void k_scan() {
    if (threadIdx.x == 0) {
        int off = 0, moff = 0;
        for (int e = 0; e < NUM_EXPERTS; e++) {
            g_offsets[e] = off; g_mtoff[e] = moff;
            off  += g_counts[e];
            moff += (g_counts[e] + BM - 1) / BM;
        }
        g_offsets[NUM_EXPERTS] = off;
        g_mtoff[NUM_EXPERTS]   = moff;
    }
}
__global__ void k_scatter(const int* __restrict__ ids) {
    int i = blockIdx.x * blockDim.x + threadIdx.x;
    if (i < NTOK) {
        int e = ids[i];
        int pos = g_offsets[e] + atomicAdd(&g_cursor[e], 1);
        g_perm[pos] = i;
    }
}

// -------- helpers --------
__device__ __forceinline__ uint32_t ldcvt(const float* p) {
    uint32_t u;
    asm("cvt.rna.tf32.f32 %0, %1;" : "=r"(u) : "f"(*p));
    return u;
}
__device__ __forceinline__ void mma_tf32(float c[4],
        uint32_t a0, uint32_t a1, uint32_t a2, uint32_t a3,
        uint32_t b0, uint32_t b1) {
    asm volatile(
        "mma.sync.aligned.m16n8k8.row.col.f32.tf32.tf32.f32 "
        "{%0,%1,%2,%3},{%4,%5,%6,%7},{%8,%9},{%0,%1,%2,%3};\n"
        : "+f"(c[0]), "+f"(c[1]), "+f"(c[2]), "+f"(c[3])
        : "r"(a0), "r"(a1), "r"(a2), "r"(a3), "r"(b0), "r"(b1));
}
__device__ __forceinline__ void cpa16(uint32_t saddr, const void* g) {
    asm volatile("cp.async.cg.shared.global [%0], [%1], 16;\n" :: "r"(saddr), "l"(g));
}
__device__ __forceinline__ void cp_commit() {
    asm volatile("cp.async.commit_group;\n" ::: "memory");
}
__device__ __forceinline__ void cp_wait1() {
    asm volatile("cp.async.wait_group 1;\n" ::: "memory");
}

__device__ __forceinline__ bool decode_tile(int bx, int NB,
        int& e, int& nt, int& m_start, int& valid) {
    int total = g_mtoff[NUM_EXPERTS] * NB;
    if (bx >= total) return false;
    e = 0;
    while (bx >= g_mtoff[e + 1] * NB) e++;
    int local = bx - g_mtoff[e] * NB;
    int mt = g_mtoff[e + 1] - g_mtoff[e];
    nt = local / mt;
    int ml = local % mt;
    m_start = g_offsets[e] + ml * BM;
    valid = g_offsets[e + 1] - m_start;
    if (valid > BM) valid = BM;
    return true;
}

// ================= GEMM1: h = silu(x@Wg^T)*(x@Wu^T)*w, grouped =================
__global__ void __launch_bounds__(THREADS, 1)
k_gemm1(const float* __restrict__ tokens,
        const float* __restrict__ gu,        // [E, 2I, D]
        const float* __restrict__ wts) {
    extern __shared__ float sm[];
    float* As = sm;                 // 2 stages x 128 x SL
    float* Bs = sm + 2 * ASZ;       // 2 stages x 128 x SL (gate rows 0-63, up 64-127)

    int e, nt, m_start, valid;
    if (!decode_tile(blockIdx.x, NB1, e, nt, m_start, valid)) return;

    const int tid  = threadIdx.x;
    const int lane = tid & 31;
    const int wm   = (tid >> 5) >> 1;   // 0..3
    const int wn   = (tid >> 5) & 1;    // 0..1

    // ---- loader mapping: 2 threads per row, 4 float4 chunks each ----
    const int lrow = tid >> 1;          // 0..127
    const int lc0  = (tid & 1) * 16;    // float offset within row
    const int arow = (lrow < valid) ? lrow : (valid - 1);
    const float* aptr = tokens + (size_t)g_perm[m_start + arow] * HIDDEN + lc0;
    const size_t gbase = (size_t)e * (2 * INTER) * HIDDEN;
    const int bglob = (lrow < 64) ? (nt * BN + lrow) : (INTER + nt * BN + lrow - 64);
    const float* bptr = gu + gbase + (size_t)bglob * HIDDEN + lc0;

    const uint32_t smem_u32 = (uint32_t)__cvta_generic_to_shared(sm);
    const uint32_t sA = smem_u32 + (uint32_t)((lrow * SL + lc0) * 4);
    const uint32_t sB = smem_u32 + (uint32_t)((2 * ASZ + lrow * SL + lc0) * 4);

    float accg[2][4][4] = {};
    float accu[2][4][4] = {};

    const int NK = HIDDEN / BK;   // 64

    // prefetch stage 0
    {
        #pragma unroll
        for (int i = 0; i < 4; i++) cpa16(sA + i * 16, aptr + i * 4);
        #pragma unroll
        for (int i = 0; i < 4; i++) cpa16(sB + i * 16, bptr + i * 4);
    }
    cp_commit();

    for (int kt = 0; kt < NK; kt++) {
        const int nstage = (kt + 1) & 1;
        if (kt + 1 < NK) {
            const int k0 = (kt + 1) * BK;
            const uint32_t dA = sA + (uint32_t)(nstage * ASZ * 4);
            const uint32_t dB = sB + (uint32_t)(nstage * B1SZ * 4);
            #pragma unroll
            for (int i = 0; i < 4; i++) cpa16(dA + i * 16, aptr + k0 + i * 4);
            #pragma unroll
            for (int i = 0; i < 4; i++) cpa16(dB + i * 16, bptr + k0 + i * 4);
        }
        cp_commit();
        cp_wait1();
        __syncthreads();

        const float* Ar = As + (kt & 1) * ASZ;
        const float* Br = Bs + (kt & 1) * B1SZ;

        #pragma unroll
        for (int ks = 0; ks < BK / 8; ks++) {
            const int kk = ks * 8 + (lane & 3);
            uint32_t a[2][4];
            #pragma unroll
            for (int im = 0; im < 2; im++) {
                const float* ab = Ar + (wm * 32 + im * 16 + (lane >> 2)) * SL + kk;
                a[im][0] = ldcvt(ab);
                a[im][1] = ldcvt(ab + 8 * SL);
                a[im][2] = ldcvt(ab + 4);
                a[im][3] = ldcvt(ab + 8 * SL + 4);
            }
            #pragma unroll
            for (int jn = 0; jn < 4; jn++) {
                const int br = wn * 32 + jn * 8 + (lane >> 2);
                const float* gb = Br + br * SL + kk;
                const float* ub = Br + (br + 64) * SL + kk;
                uint32_t bg0 = ldcvt(gb), bg1 = ldcvt(gb + 4);
                uint32_t bu0 = ldcvt(ub), bu1 = ldcvt(ub + 4);
                #pragma unroll
                for (int im = 0; im < 2; im++) {
                    mma_tf32(accg[im][jn], a[im][0], a[im][1], a[im][2], a[im][3], bg0, bg1);
                    mma_tf32(accu[im][jn], a[im][0], a[im][1], a[im][2], a[im][3], bu0, bu1);
                }
            }
        }
        __syncthreads();
    }

    // epilogue: silu(g)*u*wt -> g_h
    #pragma unroll
    for (int im = 0; im < 2; im++) {
        #pragma unroll
        for (int half = 0; half < 2; half++) {
            const int r = wm * 32 + im * 16 + half * 8 + (lane >> 2);
            if (r < valid) {
                const int s = m_start + r;
                const float wt = wts[g_perm[s]];
                float* dst = &g_h[(size_t)s * INTER + nt * BN + wn * 32 + (lane & 3) * 2];
                #pragma unroll
                for (int jn = 0; jn < 4; jn++) {
                    float g0 = accg[im][jn][half * 2 + 0];
                    float g1 = accg[im][jn][half * 2 + 1];
                    float u0 = accu[im][jn][half * 2 + 0];
                    float u1 = accu[im][jn][half * 2 + 1];
                    float2 v;
                    v.x = (g0 / (1.0f + __expf(-g0))) * u0 * wt;
                    v.y = (g1 / (1.0f + __expf(-g1))) * u1 * wt;
                    *(float2*)(dst + jn * 8) = v;
                }
            }
        }
    }
}

// ================= GEMM2: out[perm[s]] = h[s] @ down[e]^T =================
__global__ void __launch_bounds__(THREADS, 1)
k_gemm2(const float* __restrict__ down,     // [E, D, I]
        float* __restrict__ out) {
    extern __shared__ float sm[];
    float* As = sm;
    float* Bs = sm + 2 * ASZ;

    int e, nt, m_start, valid;
    if (!decode_tile(blockIdx.x, NB2, e, nt, m_start, valid)) return;

    const int tid  = threadIdx.x;
    const int lane = tid & 31;
    const int wm   = (tid >> 5) >> 1;   // 0..3
    const int wn   = (tid >> 5) & 1;    // 0..1

    // A loader: 2 threads/row, 4 chunks each
    const int larow = tid >> 1;
    const int lac0  = (tid & 1) * 16;
    const int arow = (larow < valid) ? larow : (valid - 1);
    const float* aptr = g_h + (size_t)(m_start + arow) * INTER + lac0;
    // B loader: 64 rows, 4 threads/row, 2 chunks each
    const int lbrow = tid >> 2;
    const int lbc0  = (tid & 3) * 8;
    const float* bptr = down + (size_t)e * HIDDEN * INTER
                             + (size_t)(nt * BN + lbrow) * INTER + lbc0;

    const uint32_t smem_u32 = (uint32_t)__cvta_generic_to_shared(sm);
    const uint32_t sA = smem_u32 + (uint32_t)((larow * SL + lac0) * 4);
    const uint32_t sB = smem_u32 + (uint32_t)((2 * ASZ + lbrow * SL + lbc0) * 4);

    float acc[2][4][4] = {};
    const int NK = INTER / BK;   // 44

    {
        #pragma unroll
        for (int i = 0; i < 4; i++) cpa16(sA + i * 16, aptr + i * 4);
        #pragma unroll
        for (int i = 0; i < 2; i++) cpa16(sB + i * 16, bptr + i * 4);
    }
    cp_commit();

    for (int kt = 0; kt < NK; kt++) {
        const int nstage = (kt + 1) & 1;
        if (kt + 1 < NK) {
            const int k0 = (kt + 1) * BK;
            const uint32_t dA = sA + (uint32_t)(nstage * ASZ * 4);
            const uint32_t dB = sB + (uint32_t)(nstage * B2SZ * 4);
            #pragma unroll
            for (int i = 0; i < 4; i++) cpa16(dA + i * 16, aptr + k0 + i * 4);
            #pragma unroll
            for (int i = 0; i < 2; i++) cpa16(dB + i * 16, bptr + k0 + i * 4);
        }
        cp_commit();
        cp_wait1();
        __syncthreads();

        const float* Ar = As + (kt & 1) * ASZ;
        const float* Br = Bs + (kt & 1) * B2SZ;

        #pragma unroll
        for (int ks = 0; ks < BK / 8; ks++) {
            const int kk = ks * 8 + (lane & 3);
            uint32_t a[2][4];
            #pragma unroll
            for (int im = 0; im < 2; im++) {
                const float* ab = Ar + (wm * 32 + im * 16 + (lane >> 2)) * SL + kk;
                a[im][0] = ldcvt(ab);
                a[im][1] = ldcvt(ab + 8 * SL);
                a[im][2] = ldcvt(ab + 4);
                a[im][3] = ldcvt(ab + 8 * SL + 4);
            }
            #pragma unroll
            for (int jn = 0; jn < 4; jn++) {
                const int br = wn * 32 + jn * 8 + (lane >> 2);
                const float* bb = Br + br * SL + kk;
                uint32_t b0 = ldcvt(bb), b1 = ldcvt(bb + 4);
                #pragma unroll
                for (int im = 0; im < 2; im++) {
                    mma_tf32(acc[im][jn], a[im][0], a[im][1], a[im][2], a[im][3], b0, b1);
                }
            }
        }
        __syncthreads();
    }

    #pragma unroll
    for (int im = 0; im < 2; im++) {
        #pragma unroll
        for (int half = 0; half < 2; half++) {
            const int r = wm * 32 + im * 16 + half * 8 + (lane >> 2);
            if (r < valid) {
                const int s = m_start + r;
                const int tok = g_perm[s];
                float* dst = out + (size_t)tok * HIDDEN + nt * BN + wn * 32 + (lane & 3) * 2;
                #pragma unroll
                for (int jn = 0; jn < 4; jn++) {
                    float2 v;
                    v.x = acc[im][jn][half * 2 + 0];
                    v.y = acc[im][jn][half * 2 + 1];
                    *(float2*)(dst + jn * 8) = v;
                }
            }
        }
    }
}

// -------- launch --------
extern "C" void kernel_launch(void* const* d_in, const int* in_sizes, int n_in,
                              void* d_out, int out_size) {
    const float* tokens = (const float*)d_in[0];
    const int*   ids    = (const int*)d_in[1];
    const float* wts    = (const float*)d_in[2];
    const float* gu     = (const float*)d_in[3];
    const float* down   = (const float*)d_in[4];
    float* out = (float*)d_out;

    cudaFuncSetAttribute(k_gemm1, cudaFuncAttributeMaxDynamicSharedMemorySize, SMEM1_BYTES);
    cudaFuncSetAttribute(k_gemm2, cudaFuncAttributeMaxDynamicSharedMemorySize, SMEM2_BYTES);

    k_reset<<<1, 32>>>();
    k_count<<<NTOK / 256, 256>>>(ids);
    k_scan<<<1, 32>>>();
    k_scatter<<<NTOK / 256, 256>>>(ids);

    k_gemm1<<<MAX_MTILES * NB1, THREADS, SMEM1_BYTES>>>(tokens, gu, wts);
    k_gemm2<<<MAX_MTILES * NB2, THREADS, SMEM2_BYTES>>>(down, out);
}

// round 4
// speedup vs baseline: 1.2354x; 1.2354x over previous
#include <cuda_runtime.h>
#include <cuda_fp16.h>
#include <stdint.h>

#define NUM_EXPERTS 8
#define HIDDEN 2048
#define INTER 1408
#define NTOK 8192

#define BM 128
#define THREADS 256
#define MAX_MTILES (NTOK/BM + NUM_EXPERTS - 1)   // 71
#define NB1 (INTER/64)     // 22 n-tiles (64 h-cols each; B tile = 64 gate + 64 up rows)
#define NB2 (HIDDEN/64)    // 32 n-tiles
#define NK1 (HIDDEN/32)    // 64 k-tiles
#define NK2 (INTER/32)     // 44 k-tiles
#define SA 40              // smem row stride in halfs (80B: conflict-free ldmatrix)

#define STG_A (BM*SA)          // halfs per A stage (128 rows)
#define STG_B1 (BM*SA)         // gemm1 B stage (128 rows)
#define STG_B2 (64*SA)         // gemm2 B stage (64 rows)

// -------- device scratch --------
__device__ int g_offsets[NUM_EXPERTS + 1];
__device__ int g_mtoff[NUM_EXPERTS + 1];
__device__ int g_perm[NTOK];
__device__ __half g_h[(size_t)NTOK * INTER];

// -------- router (single block) --------
__global__ void k_router(const int* __restrict__ ids) {
    __shared__ int sc[NUM_EXPERTS];
    __shared__ int sb[NUM_EXPERTS];
    int t = threadIdx.x;
    if (t < NUM_EXPERTS) sc[t] = 0;
    __syncthreads();
    for (int i = t; i < NTOK; i += THREADS) atomicAdd(&sc[ids[i]], 1);
    __syncthreads();
    if (t == 0) {
        int off = 0, moff = 0;
        for (int e = 0; e < NUM_EXPERTS; e++) {
            g_offsets[e] = off; sb[e] = off; g_mtoff[e] = moff;
            off  += sc[e];
            moff += (sc[e] + BM - 1) / BM;
        }
        g_offsets[NUM_EXPERTS] = off;
        g_mtoff[NUM_EXPERTS]   = moff;
    }
    __syncthreads();
    if (t < NUM_EXPERTS) sc[t] = 0;
    __syncthreads();
    for (int i = t; i < NTOK; i += THREADS) {
        int e = ids[i];
        g_perm[sb[e] + atomicAdd(&sc[e], 1)] = i;
    }
}

// -------- helpers --------
__device__ __forceinline__ uint32_t cvta_s(const void* p) {
    return (uint32_t)__cvta_generic_to_shared(p);
}
__device__ __forceinline__ void ldsm4(uint32_t& r0, uint32_t& r1,
                                      uint32_t& r2, uint32_t& r3, uint32_t addr) {
    asm volatile("ldmatrix.sync.aligned.m8n8.x4.shared.b16 {%0,%1,%2,%3},[%4];"
                 : "=r"(r0), "=r"(r1), "=r"(r2), "=r"(r3) : "r"(addr));
}
__device__ __forceinline__ void mma_f16(float c[4], const uint32_t a[4],
                                        uint32_t b0, uint32_t b1) {
    asm volatile(
        "mma.sync.aligned.m16n8k16.row.col.f32.f16.f16.f32 "
        "{%0,%1,%2,%3},{%4,%5,%6,%7},{%8,%9},{%0,%1,%2,%3};\n"
        : "+f"(c[0]), "+f"(c[1]), "+f"(c[2]), "+f"(c[3])
        : "r"(a[0]), "r"(a[1]), "r"(a[2]), "r"(a[3]), "r"(b0), "r"(b1));
}
__device__ __forceinline__ uint32_t pack2(float x, float y) {
    __half2 h = __floats2half2_rn(x, y);
    return *(uint32_t*)&h;
}
__device__ __forceinline__ uint4 pack8(float4 a, float4 b) {
    uint4 v;
    v.x = pack2(a.x, a.y); v.y = pack2(a.z, a.w);
    v.z = pack2(b.x, b.y); v.w = pack2(b.z, b.w);
    return v;
}

__device__ __forceinline__ bool decode_tile(int bx, int NB,
        int& e, int& nt, int& m_start, int& valid) {
    int total = g_mtoff[NUM_EXPERTS] * NB;
    if (bx >= total) return false;
    e = 0;
    while (bx >= g_mtoff[e + 1] * NB) e++;
    int local = bx - g_mtoff[e] * NB;
    int mt = g_mtoff[e + 1] - g_mtoff[e];
    nt = local / mt;
    int ml = local % mt;
    m_start = g_offsets[e] + ml * BM;
    valid = g_offsets[e + 1] - m_start;
    if (valid > BM) valid = BM;
    return true;
}

// ================= GEMM1: h = silu(x@Wg^T)*(x@Wu^T)*w =================
__global__ void __launch_bounds__(THREADS)
k_gemm1(const float* __restrict__ tokens,
        const float* __restrict__ gu,        // [E, 2I, D]
        const float* __restrict__ wts) {
    __shared__ __align__(16) __half smA[2][STG_A];
    __shared__ __align__(16) __half smB[2][STG_B1];   // rows 0-63 gate, 64-127 up

    int e, nt, m_start, valid;
    if (!decode_tile(blockIdx.x, NB1, e, nt, m_start, valid)) return;

    const int tid = threadIdx.x;
    const int lane = tid & 31;
    const int wid = tid >> 5;
    const int wm = wid >> 1;    // 0..3
    const int wn = wid & 1;     // 0..1
    const int n0 = nt * 64;

    // ---- loaders: 2 threads per row, 16 floats each ----
    const int lr = tid >> 1;
    const int lc = (tid & 1) * 16;
    const int arc = (lr < valid) ? lr : (valid - 1);
    const float* asrc = tokens + (size_t)g_perm[m_start + arc] * HIDDEN + lc;
    const int brow = (lr < 64) ? (n0 + lr) : (INTER + n0 + lr - 64);
    const float* bsrc = gu + (size_t)e * 2 * INTER * HIDDEN + (size_t)brow * HIDDEN + lc;

    __half* stA = &smA[0][lr * SA + lc];
    __half* stB = &smB[0][lr * SA + lc];

    // ---- fragment addresses ----
    const uint32_t aBase = cvta_s(&smA[0][0]) +
        (((wm * 32 + (lane & 15)) * SA + (lane >> 4) * 8) << 1);
    const uint32_t bBase = cvta_s(&smB[0][0]) +
        (((wn * 32 + ((lane >> 4) * 8) + (lane & 7)) * SA + ((lane >> 3) & 1) * 8) << 1);

    float accg[2][4][4] = {};
    float accu[2][4][4] = {};
    float4 ra[4], rb[4];

#pragma unroll
    for (int i = 0; i < 4; i++) {
        ra[i] = *(const float4*)(asrc + i * 4);
        rb[i] = *(const float4*)(bsrc + i * 4);
    }

    for (int kt = 0; kt < NK1; kt++) {
        const int st = kt & 1;
        *(uint4*)(stA + st * STG_A)     = pack8(ra[0], ra[1]);
        *(uint4*)(stA + st * STG_A + 8) = pack8(ra[2], ra[3]);
        *(uint4*)(stB + st * STG_B1)     = pack8(rb[0], rb[1]);
        *(uint4*)(stB + st * STG_B1 + 8) = pack8(rb[2], rb[3]);
        __syncthreads();

        if (kt + 1 < NK1) {
            const float* an = asrc + (kt + 1) * 32;
            const float* bn = bsrc + (kt + 1) * 32;
#pragma unroll
            for (int i = 0; i < 4; i++) {
                ra[i] = *(const float4*)(an + i * 4);
                rb[i] = *(const float4*)(bn + i * 4);
            }
        }

        const uint32_t aS = aBase + st * (STG_A * 2);
        const uint32_t bS = bBase + st * (STG_B1 * 2);
#pragma unroll
        for (int ks = 0; ks < 2; ks++) {
            uint32_t a[2][4];
#pragma unroll
            for (int im = 0; im < 2; im++)
                ldsm4(a[im][0], a[im][1], a[im][2], a[im][3],
                      aS + ((im * 16 * SA + ks * 16) << 1));
#pragma unroll
            for (int jp = 0; jp < 2; jp++) {
                uint32_t g0, g1, g2, g3, u0, u1, u2, u3;
                ldsm4(g0, g1, g2, g3, bS + ((jp * 16 * SA + ks * 16) << 1));
                ldsm4(u0, u1, u2, u3, bS + (((64 + jp * 16) * SA + ks * 16) << 1));
#pragma unroll
                for (int im = 0; im < 2; im++) {
                    mma_f16(accg[im][jp * 2],     a[im], g0, g1);
                    mma_f16(accg[im][jp * 2 + 1], a[im], g2, g3);
                    mma_f16(accu[im][jp * 2],     a[im], u0, u1);
                    mma_f16(accu[im][jp * 2 + 1], a[im], u2, u3);
                }
            }
        }
    }

    // ---- epilogue: silu(g)*u*wt -> g_h (fp16), straight from fragments ----
#pragma unroll
    for (int im = 0; im < 2; im++) {
#pragma unroll
        for (int half = 0; half < 2; half++) {
            const int r = wm * 32 + im * 16 + half * 8 + (lane >> 2);
            if (r < valid) {
                const int s = m_start + r;
                const float wt = wts[g_perm[s]];
                __half* dst = g_h + (size_t)s * INTER + n0 + wn * 32 + (lane & 3) * 2;
#pragma unroll
                for (int jn = 0; jn < 4; jn++) {
                    float gx = accg[im][jn][half * 2 + 0];
                    float gy = accg[im][jn][half * 2 + 1];
                    float ux = accu[im][jn][half * 2 + 0];
                    float uy = accu[im][jn][half * 2 + 1];
                    float hx = (gx / (1.0f + __expf(-gx))) * ux * wt;
                    float hy = (gy / (1.0f + __expf(-gy))) * uy * wt;
                    *(__half2*)(dst + jn * 8) = __floats2half2_rn(hx, hy);
                }
            }
        }
    }
}

// ================= GEMM2: out[perm[s]] = h[s] @ down[e]^T =================
__global__ void __launch_bounds__(THREADS)
k_gemm2(const float* __restrict__ down,     // [E, D, I]
        float* __restrict__ out) {
    __shared__ __align__(16) __half smA[2][STG_A];
    __shared__ __align__(16) __half smB[2][STG_B2];

    int e, nt, m_start, valid;
    if (!decode_tile(blockIdx.x, NB2, e, nt, m_start, valid)) return;

    const int tid = threadIdx.x;
    const int lane = tid & 31;
    const int wid = tid >> 5;
    const int wm = wid >> 1;
    const int wn = wid & 1;
    const int n0 = nt * 64;

    // A loader: fp16 source (g_h), 2 threads/row, 16 halfs each
    const int lr = tid >> 1;
    const int lc = (tid & 1) * 16;
    const int arc = (lr < valid) ? lr : (valid - 1);
    const __half* asrc = g_h + (size_t)(m_start + arc) * INTER + lc;
    // B loader: fp32 source, 4 threads/row (64 rows), 8 floats each
    const int br = tid >> 2;
    const int bc = (tid & 3) * 8;
    const float* bsrc = down + (size_t)e * HIDDEN * INTER + (size_t)(n0 + br) * INTER + bc;

    __half* stA = &smA[0][lr * SA + lc];
    __half* stB = &smB[0][br * SA + bc];

    const uint32_t aBase = cvta_s(&smA[0][0]) +
        (((wm * 32 + (lane & 15)) * SA + (lane >> 4) * 8) << 1);
    const uint32_t bBase = cvta_s(&smB[0][0]) +
        (((wn * 32 + ((lane >> 4) * 8) + (lane & 7)) * SA + ((lane >> 3) & 1) * 8) << 1);

    float acc[2][4][4] = {};
    uint4 ua[2];
    float4 rb[2];

    ua[0] = *(const uint4*)(asrc);
    ua[1] = *(const uint4*)(asrc + 8);
    rb[0] = *(const float4*)(bsrc);
    rb[1] = *(const float4*)(bsrc + 4);

    for (int kt = 0; kt < NK2; kt++) {
        const int st = kt & 1;
        *(uint4*)(stA + st * STG_A)     = ua[0];
        *(uint4*)(stA + st * STG_A + 8) = ua[1];
        *(uint4*)(stB + st * STG_B2)    = pack8(rb[0], rb[1]);
        __syncthreads();

        if (kt + 1 < NK2) {
            const __half* an = asrc + (kt + 1) * 32;
            const float* bn = bsrc + (kt + 1) * 32;
            ua[0] = *(const uint4*)(an);
            ua[1] = *(const uint4*)(an + 8);
            rb[0] = *(const float4*)(bn);
            rb[1] = *(const float4*)(bn + 4);
        }

        const uint32_t aS = aBase + st * (STG_A * 2);
        const uint32_t bS = bBase + st * (STG_B2 * 2);
#pragma unroll
        for (int ks = 0; ks < 2; ks++) {
            uint32_t a[2][4];
#pragma unroll
            for (int im = 0; im < 2; im++)
                ldsm4(a[im][0], a[im][1], a[im][2], a[im][3],
                      aS + ((im * 16 * SA + ks * 16) << 1));
#pragma unroll
            for (int jp = 0; jp < 2; jp++) {
                uint32_t b0, b1, b2, b3;
                ldsm4(b0, b1, b2, b3, bS + ((jp * 16 * SA + ks * 16) << 1));
#pragma unroll
                for (int im = 0; im < 2; im++) {
                    mma_f16(acc[im][jp * 2],     a[im], b0, b1);
                    mma_f16(acc[im][jp * 2 + 1], a[im], b2, b3);
                }
            }
        }
    }

#pragma unroll
    for (int im = 0; im < 2; im++) {
#pragma unroll
        for (int half = 0; half < 2; half++) {
            const int r = wm * 32 + im * 16 + half * 8 + (lane >> 2);
            if (r < valid) {
                const int tok = g_perm[m_start + r];
                float* dst = out + (size_t)tok * HIDDEN + n0 + wn * 32 + (lane & 3) * 2;
#pragma unroll
                for (int jn = 0; jn < 4; jn++) {
                    float2 v;
                    v.x = acc[im][jn][half * 2 + 0];
                    v.y = acc[im][jn][half * 2 + 1];
                    *(float2*)(dst + jn * 8) = v;
                }
            }
        }
    }
}

// -------- launch --------
extern "C" void kernel_launch(void* const* d_in, const int* in_sizes, int n_in,
                              void* d_out, int out_size) {
    const float* tokens = (const float*)d_in[0];
    const int*   ids    = (const int*)d_in[1];
    const float* wts    = (const float*)d_in[2];
    const float* gu     = (const float*)d_in[3];
    const float* down   = (const float*)d_in[4];
    float* out = (float*)d_out;

    k_router<<<1, THREADS>>>(ids);
    k_gemm1<<<MAX_MTILES * NB1, THREADS>>>(tokens, gu, wts);
    k_gemm2<<<MAX_MTILES * NB2, THREADS>>>(down, out);
}

// round 5
// speedup vs baseline: 1.5598x; 1.2626x over previous
#include <cuda_runtime.h>
#include <cuda_fp16.h>
#include <stdint.h>

#define NUM_EXPERTS 8
#define HIDDEN 2048
#define INTER 1408
#define NTOK 8192

#define BM 128
#define THREADS 256
#define MAX_MTILES (NTOK/BM + NUM_EXPERTS - 1)   // 71
#define NB1 (INTER/64)     // 22 n-tiles (64 h-cols; B tile = 64 gate + 64 up rows)
#define NB2 (HIDDEN/128)   // 16 n-tiles (128 out-cols)
#define NK1 (HIDDEN/32)    // 64
#define NK2 (INTER/32)     // 44
#define SA 40              // smem row stride (halfs)

#define STG_A (BM*SA)
#define STG_B (BM*SA)

// -------- device scratch (fp16 copies, converted once per call) --------
__device__ int g_offsets[NUM_EXPERTS + 1];
__device__ int g_mtoff[NUM_EXPERTS + 1];
__device__ int g_perm[NTOK];
__device__ __half g_w1[(size_t)NUM_EXPERTS * 2 * INTER * HIDDEN];  // 92MB
__device__ __half g_w2[(size_t)NUM_EXPERTS * HIDDEN * INTER];      // 46MB
__device__ __half g_x[(size_t)NTOK * HIDDEN];                      // permuted fp16 tokens
__device__ __half g_h[(size_t)NTOK * INTER];

// -------- helpers --------
__device__ __forceinline__ uint32_t cvta_s(const void* p) {
    return (uint32_t)__cvta_generic_to_shared(p);
}
__device__ __forceinline__ void ldsm4(uint32_t& r0, uint32_t& r1,
                                      uint32_t& r2, uint32_t& r3, uint32_t addr) {
    asm volatile("ldmatrix.sync.aligned.m8n8.x4.shared.b16 {%0,%1,%2,%3},[%4];"
                 : "=r"(r0), "=r"(r1), "=r"(r2), "=r"(r3) : "r"(addr));
}
__device__ __forceinline__ void mma_f16(float c[4], const uint32_t a[4],
                                        uint32_t b0, uint32_t b1) {
    asm volatile(
        "mma.sync.aligned.m16n8k16.row.col.f32.f16.f16.f32 "
        "{%0,%1,%2,%3},{%4,%5,%6,%7},{%8,%9},{%0,%1,%2,%3};\n"
        : "+f"(c[0]), "+f"(c[1]), "+f"(c[2]), "+f"(c[3])
        : "r"(a[0]), "r"(a[1]), "r"(a[2]), "r"(a[3]), "r"(b0), "r"(b1));
}
__device__ __forceinline__ uint32_t pack2(float x, float y) {
    __half2 h = __floats2half2_rn(x, y);
    return *(uint32_t*)&h;
}
__device__ __forceinline__ uint4 pack8(float4 a, float4 b) {
    uint4 v;
    v.x = pack2(a.x, a.y); v.y = pack2(a.z, a.w);
    v.z = pack2(b.x, b.y); v.w = pack2(b.z, b.w);
    return v;
}

// -------- router (single block) --------
__global__ void k_router(const int* __restrict__ ids) {
    __shared__ int sc[NUM_EXPERTS];
    __shared__ int sb[NUM_EXPERTS];
    int t = threadIdx.x;
    if (t < NUM_EXPERTS) sc[t] = 0;
    __syncthreads();
    for (int i = t; i < NTOK; i += THREADS) atomicAdd(&sc[ids[i]], 1);
    __syncthreads();
    if (t == 0) {
        int off = 0, moff = 0;
        for (int e = 0; e < NUM_EXPERTS; e++) {
            g_offsets[e] = off; sb[e] = off; g_mtoff[e] = moff;
            off  += sc[e];
            moff += (sc[e] + BM - 1) / BM;
        }
        g_offsets[NUM_EXPERTS] = off;
        g_mtoff[NUM_EXPERTS]   = moff;
    }
    __syncthreads();
    if (t < NUM_EXPERTS) sc[t] = 0;
    __syncthreads();
    for (int i = t; i < NTOK; i += THREADS) {
        int e = ids[i];
        g_perm[sb[e] + atomicAdd(&sc[e], 1)] = i;
    }
}

// -------- pre-convert: fp32 -> fp16 (vectorized, memory bound) --------
__global__ void k_cvt(const float* __restrict__ src, __half* __restrict__ dst, int n8) {
    int i = blockIdx.x * blockDim.x + threadIdx.x;
    if (i < n8) {
        const float4* s = (const float4*)src + 2 * (size_t)i;
        float4 a = s[0], b = s[1];
        ((uint4*)dst)[i] = pack8(a, b);
    }
}

// -------- gather tokens into permuted fp16 rows --------
__global__ void k_gather(const float* __restrict__ tokens) {
    const int s = blockIdx.x;
    const int tok = g_perm[s];
    const float4* src = (const float4*)(tokens + (size_t)tok * HIDDEN);
    uint4* dst = (uint4*)(g_x + (size_t)s * HIDDEN);
    for (int i = threadIdx.x; i < HIDDEN / 8; i += THREADS)
        dst[i] = pack8(src[2 * i], src[2 * i + 1]);
}

__device__ __forceinline__ bool decode_tile(int bx, int NB,
        int& e, int& nt, int& m_start, int& valid) {
    int total = g_mtoff[NUM_EXPERTS] * NB;
    if (bx >= total) return false;
    e = 0;
    while (bx >= g_mtoff[e + 1] * NB) e++;
    int local = bx - g_mtoff[e] * NB;
    int mt = g_mtoff[e + 1] - g_mtoff[e];
    nt = local / mt;
    int ml = local % mt;
    m_start = g_offsets[e] + ml * BM;
    valid = g_offsets[e + 1] - m_start;
    if (valid > BM) valid = BM;
    return true;
}

// ================= GEMM1: h = silu(x@Wg^T)*(x@Wu^T)*w =================
__global__ void __launch_bounds__(THREADS)
k_gemm1(const float* __restrict__ wts) {
    __shared__ __align__(16) __half smA[2][STG_A];
    __shared__ __align__(16) __half smB[2][STG_B];   // rows 0-63 gate, 64-127 up

    int e, nt, m_start, valid;
    if (!decode_tile(blockIdx.x, NB1, e, nt, m_start, valid)) return;

    const int tid = threadIdx.x;
    const int lane = tid & 31;
    const int wid = tid >> 5;
    const int wm = wid >> 1;
    const int wn = wid & 1;
    const int n0 = nt * 64;

    // loaders: 2 threads per row, 16 halfs each
    const int lr = tid >> 1;
    const int lc = (tid & 1) * 16;
    const int arc = (lr < valid) ? lr : (valid - 1);
    const __half* asrc = g_x + (size_t)(m_start + arc) * HIDDEN + lc;
    const int brow = (lr < 64) ? (n0 + lr) : (INTER + n0 + lr - 64);
    const __half* bsrc = g_w1 + (size_t)e * 2 * INTER * HIDDEN + (size_t)brow * HIDDEN + lc;

    __half* stA = &smA[0][lr * SA + lc];
    __half* stB = &smB[0][lr * SA + lc];

    const uint32_t aBase = cvta_s(&smA[0][0]) +
        (((wm * 32 + (lane & 15)) * SA + (lane >> 4) * 8) << 1);
    const uint32_t bBase = cvta_s(&smB[0][0]) +
        (((wn * 32 + ((lane >> 4) * 8) + (lane & 7)) * SA + ((lane >> 3) & 1) * 8) << 1);

    float accg[2][4][4] = {};
    float accu[2][4][4] = {};
    uint4 ua[2], ub[2];

    ua[0] = *(const uint4*)(asrc);
    ua[1] = *(const uint4*)(asrc + 8);
    ub[0] = *(const uint4*)(bsrc);
    ub[1] = *(const uint4*)(bsrc + 8);

    for (int kt = 0; kt < NK1; kt++) {
        const int st = kt & 1;
        *(uint4*)(stA + st * STG_A)     = ua[0];
        *(uint4*)(stA + st * STG_A + 8) = ua[1];
        *(uint4*)(stB + st * STG_B)     = ub[0];
        *(uint4*)(stB + st * STG_B + 8) = ub[1];
        __syncthreads();

        if (kt + 1 < NK1) {
            const __half* an = asrc + (kt + 1) * 32;
            const __half* bn = bsrc + (kt + 1) * 32;
            ua[0] = *(const uint4*)(an);
            ua[1] = *(const uint4*)(an + 8);
            ub[0] = *(const uint4*)(bn);
            ub[1] = *(const uint4*)(bn + 8);
        }

        const uint32_t aS = aBase + st * (STG_A * 2);
        const uint32_t bS = bBase + st * (STG_B * 2);
#pragma unroll
        for (int ks = 0; ks < 2; ks++) {
            uint32_t a[2][4];
#pragma unroll
            for (int im = 0; im < 2; im++)
                ldsm4(a[im][0], a[im][1], a[im][2], a[im][3],
                      aS + ((im * 16 * SA + ks * 16) << 1));
#pragma unroll
            for (int jp = 0; jp < 2; jp++) {
                uint32_t g0, g1, g2, g3, u0, u1, u2, u3;
                ldsm4(g0, g1, g2, g3, bS + ((jp * 16 * SA + ks * 16) << 1));
                ldsm4(u0, u1, u2, u3, bS + (((64 + jp * 16) * SA + ks * 16) << 1));
#pragma unroll
                for (int im = 0; im < 2; im++) {
                    mma_f16(accg[im][jp * 2],     a[im], g0, g1);
                    mma_f16(accg[im][jp * 2 + 1], a[im], g2, g3);
                    mma_f16(accu[im][jp * 2],     a[im], u0, u1);
                    mma_f16(accu[im][jp * 2 + 1], a[im], u2, u3);
                }
            }
        }
    }

    // epilogue: silu(g)*u*wt -> g_h (fp16)
#pragma unroll
    for (int im = 0; im < 2; im++) {
#pragma unroll
        for (int half = 0; half < 2; half++) {
            const int r = wm * 32 + im * 16 + half * 8 + (lane >> 2);
            if (r < valid) {
                const int s = m_start + r;
                const float wt = wts[g_perm[s]];
                __half* dst = g_h + (size_t)s * INTER + n0 + wn * 32 + (lane & 3) * 2;
#pragma unroll
                for (int jn = 0; jn < 4; jn++) {
                    float gx = accg[im][jn][half * 2 + 0];
                    float gy = accg[im][jn][half * 2 + 1];
                    float ux = accu[im][jn][half * 2 + 0];
                    float uy = accu[im][jn][half * 2 + 1];
                    float hx = (gx / (1.0f + __expf(-gx))) * ux * wt;
                    float hy = (gy / (1.0f + __expf(-gy))) * uy * wt;
                    *(__half2*)(dst + jn * 8) = __floats2half2_rn(hx, hy);
                }
            }
        }
    }
}

// ================= GEMM2: out[perm[s]] = h[s] @ down[e]^T (BN=128) =================
__global__ void __launch_bounds__(THREADS)
k_gemm2(float* __restrict__ out) {
    __shared__ __align__(16) __half smA[2][STG_A];
    __shared__ __align__(16) __half smB[2][STG_B];

    int e, nt, m_start, valid;
    if (!decode_tile(blockIdx.x, NB2, e, nt, m_start, valid)) return;

    const int tid = threadIdx.x;
    const int lane = tid & 31;
    const int wid = tid >> 5;
    const int wm = wid >> 1;    // 0..3 : 32 m-rows each
    const int wn = wid & 1;     // 0..1 : 64 n-cols each
    const int n0 = nt * 128;

    const int lr = tid >> 1;
    const int lc = (tid & 1) * 16;
    const int arc = (lr < valid) ? lr : (valid - 1);
    const __half* asrc = g_h + (size_t)(m_start + arc) * INTER + lc;
    const __half* bsrc = g_w2 + (size_t)e * HIDDEN * INTER + (size_t)(n0 + lr) * INTER + lc;

    __half* stA = &smA[0][lr * SA + lc];
    __half* stB = &smB[0][lr * SA + lc];

    const uint32_t aBase = cvta_s(&smA[0][0]) +
        (((wm * 32 + (lane & 15)) * SA + (lane >> 4) * 8) << 1);
    const uint32_t bBase = cvta_s(&smB[0][0]) +
        (((wn * 64 + ((lane >> 4) * 8) + (lane & 7)) * SA + ((lane >> 3) & 1) * 8) << 1);

    float acc[2][8][4] = {};
    uint4 ua[2], ub[2];

    ua[0] = *(const uint4*)(asrc);
    ua[1] = *(const uint4*)(asrc + 8);
    ub[0] = *(const uint4*)(bsrc);
    ub[1] = *(const uint4*)(bsrc + 8);

    for (int kt = 0; kt < NK2; kt++) {
        const int st = kt & 1;
        *(uint4*)(stA + st * STG_A)     = ua[0];
        *(uint4*)(stA + st * STG_A + 8) = ua[1];
        *(uint4*)(stB + st * STG_B)     = ub[0];
        *(uint4*)(stB + st * STG_B + 8) = ub[1];
        __syncthreads();

        if (kt + 1 < NK2) {
            const __half* an = asrc + (kt + 1) * 32;
            const __half* bn = bsrc + (kt + 1) * 32;
            ua[0] = *(const uint4*)(an);
            ua[1] = *(const uint4*)(an + 8);
            ub[0] = *(const uint4*)(bn);
            ub[1] = *(const uint4*)(bn + 8);
        }

        const uint32_t aS = aBase + st * (STG_A * 2);
        const uint32_t bS = bBase + st * (STG_B * 2);
#pragma unroll
        for (int ks = 0; ks < 2; ks++) {
            uint32_t a[2][4];
#pragma unroll
            for (int im = 0; im < 2; im++)
                ldsm4(a[im][0], a[im][1], a[im][2], a[im][3],
                      aS + ((im * 16 * SA + ks * 16) << 1));
#pragma unroll
            for (int jp = 0; jp < 4; jp++) {
                uint32_t b0, b1, b2, b3;
                ldsm4(b0, b1, b2, b3, bS + ((jp * 16 * SA + ks * 16) << 1));
#pragma unroll
                for (int im = 0; im < 2; im++) {
                    mma_f16(acc[im][jp * 2],     a[im], b0, b1);
                    mma_f16(acc[im][jp * 2 + 1], a[im], b2, b3);
                }
            }
        }
    }

#pragma unroll
    for (int im = 0; im < 2; im++) {
#pragma unroll
        for (int half = 0; half < 2; half++) {
            const int r = wm * 32 + im * 16 + half * 8 + (lane >> 2);
            if (r < valid) {
                const int tok = g_perm[m_start + r];
                float* dst = out + (size_t)tok * HIDDEN + n0 + wn * 64 + (lane & 3) * 2;
#pragma unroll
                for (int jn = 0; jn < 8; jn++) {
                    float2 v;
                    v.x = acc[im][jn][half * 2 + 0];
                    v.y = acc[im][jn][half * 2 + 1];
                    *(float2*)(dst + jn * 8) = v;
                }
            }
        }
    }
}

// -------- launch --------
extern "C" void kernel_launch(void* const* d_in, const int* in_sizes, int n_in,
                              void* d_out, int out_size) {
    const float* tokens = (const float*)d_in[0];
    const int*   ids    = (const int*)d_in[1];
    const float* wts    = (const float*)d_in[2];
    const float* gu     = (const float*)d_in[3];
    const float* down   = (const float*)d_in[4];
    float* out = (float*)d_out;

    __half* w1p; cudaGetSymbolAddress((void**)&w1p, g_w1);
    __half* w2p; cudaGetSymbolAddress((void**)&w2p, g_w2);

    const int n8_w1 = NUM_EXPERTS * 2 * INTER * HIDDEN / 8;
    const int n8_w2 = NUM_EXPERTS * HIDDEN * INTER / 8;

    k_router<<<1, THREADS>>>(ids);
    k_cvt<<<(n8_w1 + 255) / 256, 256>>>(gu, w1p, n8_w1);
    k_cvt<<<(n8_w2 + 255) / 256, 256>>>(down, w2p, n8_w2);
    k_gather<<<NTOK, THREADS>>>(tokens);

    k_gemm1<<<MAX_MTILES * NB1, THREADS>>>(wts);
    k_gemm2<<<MAX_MTILES * NB2, THREADS>>>(out);
}

// round 6
// speedup vs baseline: 2.3664x; 1.5171x over previous
#include <cuda_runtime.h>
#include <cuda_fp16.h>
#include <stdint.h>

#define NUM_EXPERTS 8
#define HIDDEN 2048
#define INTER 1408
#define NTOK 8192

#define BM 128
#define THREADS 256
#define MAX_MTILES (NTOK/BM + NUM_EXPERTS - 1)   // 71
#define NB1 (INTER/64)     // 22
#define NB2 (HIDDEN/128)   // 16
#define NK1 (HIDDEN/32)    // 64
#define NK2 (INTER/32)     // 44
#define SA 40              // smem row stride (halfs), conflict-free ldsm

#define STG (BM*SA)            // 5120 halfs = 10240 B per stage per operand
#define STG_BYTES (STG*2)
#define NSTAGE 4
#define SMEM_BYTES (2*NSTAGE*STG_BYTES)   // 81920

// -------- device scratch --------
__device__ int g_offsets[NUM_EXPERTS + 1];
__device__ int g_mtoff[NUM_EXPERTS + 1];
__device__ int g_perm[NTOK];
__device__ __half g_w1[(size_t)NUM_EXPERTS * 2 * INTER * HIDDEN];
__device__ __half g_w2[(size_t)NUM_EXPERTS * HIDDEN * INTER];
__device__ __half g_x[(size_t)NTOK * HIDDEN];
__device__ __half g_h[(size_t)NTOK * INTER];

// -------- helpers --------
__device__ __forceinline__ uint32_t cvta_s(const void* p) {
    return (uint32_t)__cvta_generic_to_shared(p);
}
__device__ __forceinline__ void ldsm4(uint32_t& r0, uint32_t& r1,
                                      uint32_t& r2, uint32_t& r3, uint32_t addr) {
    asm volatile("ldmatrix.sync.aligned.m8n8.x4.shared.b16 {%0,%1,%2,%3},[%4];"
                 : "=r"(r0), "=r"(r1), "=r"(r2), "=r"(r3) : "r"(addr));
}
__device__ __forceinline__ void mma_f16(float c[4], const uint32_t a[4],
                                        uint32_t b0, uint32_t b1) {
    asm volatile(
        "mma.sync.aligned.m16n8k16.row.col.f32.f16.f16.f32 "
        "{%0,%1,%2,%3},{%4,%5,%6,%7},{%8,%9},{%0,%1,%2,%3};\n"
        : "+f"(c[0]), "+f"(c[1]), "+f"(c[2]), "+f"(c[3])
        : "r"(a[0]), "r"(a[1]), "r"(a[2]), "r"(a[3]), "r"(b0), "r"(b1));
}
__device__ __forceinline__ void cpa16(uint32_t s, const void* g) {
    asm volatile("cp.async.cg.shared.global [%0], [%1], 16;\n" :: "r"(s), "l"(g));
}
__device__ __forceinline__ void cp_commit() {
    asm volatile("cp.async.commit_group;\n" ::: "memory");
}
__device__ __forceinline__ void cp_wait2() {
    asm volatile("cp.async.wait_group 2;\n" ::: "memory");
}
__device__ __forceinline__ uint32_t pack2(float x, float y) {
    __half2 h = __floats2half2_rn(x, y);
    return *(uint32_t*)&h;
}
__device__ __forceinline__ uint4 pack8(float4 a, float4 b) {
    uint4 v;
    v.x = pack2(a.x, a.y); v.y = pack2(a.z, a.w);
    v.z = pack2(b.x, b.y); v.w = pack2(b.z, b.w);
    return v;
}

// -------- router --------
__global__ void k_router(const int* __restrict__ ids) {
    __shared__ int sc[NUM_EXPERTS];
    __shared__ int sb[NUM_EXPERTS];
    int t = threadIdx.x;
    if (t < NUM_EXPERTS) sc[t] = 0;
    __syncthreads();
    for (int i = t; i < NTOK; i += THREADS) atomicAdd(&sc[ids[i]], 1);
    __syncthreads();
    if (t == 0) {
        int off = 0, moff = 0;
        for (int e = 0; e < NUM_EXPERTS; e++) {
            g_offsets[e] = off; sb[e] = off; g_mtoff[e] = moff;
            off  += sc[e];
            moff += (sc[e] + BM - 1) / BM;
        }
        g_offsets[NUM_EXPERTS] = off;
        g_mtoff[NUM_EXPERTS]   = moff;
    }
    __syncthreads();
    if (t < NUM_EXPERTS) sc[t] = 0;
    __syncthreads();
    for (int i = t; i < NTOK; i += THREADS) {
        int e = ids[i];
        g_perm[sb[e] + atomicAdd(&sc[e], 1)] = i;
    }
}

// -------- pre-convert fp32 -> fp16 --------
__global__ void k_cvt(const float* __restrict__ src, __half* __restrict__ dst, int n8) {
    int i = blockIdx.x * blockDim.x + threadIdx.x;
    if (i < n8) {
        const float4* s = (const float4*)src + 2 * (size_t)i;
        ((uint4*)dst)[i] = pack8(s[0], s[1]);
    }
}

// -------- gather permuted fp16 tokens --------
__global__ void k_gather(const float* __restrict__ tokens) {
    const int s = blockIdx.x;
    const int tok = g_perm[s];
    const float4* src = (const float4*)(tokens + (size_t)tok * HIDDEN);
    uint4* dst = (uint4*)(g_x + (size_t)s * HIDDEN);
    for (int i = threadIdx.x; i < HIDDEN / 8; i += THREADS)
        dst[i] = pack8(src[2 * i], src[2 * i + 1]);
}

__device__ __forceinline__ bool decode_tile(int bx, int NB,
        int& e, int& nt, int& m_start, int& valid) {
    int total = g_mtoff[NUM_EXPERTS] * NB;
    if (bx >= total) return false;
    e = 0;
    while (bx >= g_mtoff[e + 1] * NB) e++;
    int local = bx - g_mtoff[e] * NB;
    int mt = g_mtoff[e + 1] - g_mtoff[e];
    nt = local / mt;
    int ml = local % mt;
    m_start = g_offsets[e] + ml * BM;
    valid = g_offsets[e + 1] - m_start;
    if (valid > BM) valid = BM;
    return true;
}

// ================= GEMM1 =================
__global__ void __launch_bounds__(THREADS)
k_gemm1(const float* __restrict__ wts) {
    extern __shared__ __half sm[];

    int e, nt, m_start, valid;
    if (!decode_tile(blockIdx.x, NB1, e, nt, m_start, valid)) return;

    const int tid = threadIdx.x;
    const int lane = tid & 31;
    const int wid = tid >> 5;
    const int wm = wid >> 1;
    const int wn = wid & 1;
    const int n0 = nt * 64;

    const int lr = tid >> 1;
    const int lc = (tid & 1) * 16;
    const int arc = (lr < valid) ? lr : (valid - 1);
    const __half* aptr = g_x + (size_t)(m_start + arc) * HIDDEN + lc;
    const int brow = (lr < 64) ? (n0 + lr) : (INTER + n0 + lr - 64);
    const __half* bptr = g_w1 + (size_t)e * 2 * INTER * HIDDEN + (size_t)brow * HIDDEN + lc;

    const uint32_t smb = cvta_s(sm);
    const uint32_t sAst = smb + (lr * SA + lc) * 2;
    const uint32_t sBst = smb + NSTAGE * STG_BYTES + (lr * SA + lc) * 2;
    const uint32_t aBase = smb + ((wm * 32 + (lane & 15)) * SA + (lane >> 4) * 8) * 2;
    const uint32_t bBase = smb + NSTAGE * STG_BYTES +
        ((wn * 32 + ((lane >> 4) * 8) + (lane & 7)) * SA + ((lane >> 3) & 1) * 8) * 2;

    float accg[2][4][4] = {};
    float accu[2][4][4] = {};

    auto issue = [&](int kt) {
        if (kt < NK1) {
            const int st = kt & (NSTAGE - 1);
            const __half* a = aptr + kt * 32;
            const __half* b = bptr + kt * 32;
            cpa16(sAst + st * STG_BYTES,      a);
            cpa16(sAst + st * STG_BYTES + 16, a + 8);
            cpa16(sBst + st * STG_BYTES,      b);
            cpa16(sBst + st * STG_BYTES + 16, b + 8);
        }
        cp_commit();
    };

    issue(0); issue(1); issue(2);

    for (int kt = 0; kt < NK1; kt++) {
        cp_wait2();
        __syncthreads();
        issue(kt + 3);

        const int st = kt & (NSTAGE - 1);
        const uint32_t aS = aBase + st * STG_BYTES;
        const uint32_t bS = bBase + st * STG_BYTES;
#pragma unroll
        for (int ks = 0; ks < 2; ks++) {
            uint32_t a[2][4];
#pragma unroll
            for (int im = 0; im < 2; im++)
                ldsm4(a[im][0], a[im][1], a[im][2], a[im][3],
                      aS + ((im * 16 * SA + ks * 16) << 1));
#pragma unroll
            for (int jp = 0; jp < 2; jp++) {
                uint32_t g0, g1, g2, g3, u0, u1, u2, u3;
                ldsm4(g0, g1, g2, g3, bS + ((jp * 16 * SA + ks * 16) << 1));
                ldsm4(u0, u1, u2, u3, bS + (((64 + jp * 16) * SA + ks * 16) << 1));
#pragma unroll
                for (int im = 0; im < 2; im++) {
                    mma_f16(accg[im][jp * 2],     a[im], g0, g1);
                    mma_f16(accg[im][jp * 2 + 1], a[im], g2, g3);
                    mma_f16(accu[im][jp * 2],     a[im], u0, u1);
                    mma_f16(accu[im][jp * 2 + 1], a[im], u2, u3);
                }
            }
        }
        __syncthreads();
    }

    // epilogue: silu(g)*u*wt -> g_h (fp16)
#pragma unroll
    for (int im = 0; im < 2; im++) {
#pragma unroll
        for (int half = 0; half < 2; half++) {
            const int r = wm * 32 + im * 16 + half * 8 + (lane >> 2);
            if (r < valid) {
                const int s = m_start + r;
                const float wt = wts[g_perm[s]];
                __half* dst = g_h + (size_t)s * INTER + n0 + wn * 32 + (lane & 3) * 2;
#pragma unroll
                for (int jn = 0; jn < 4; jn++) {
                    float gx = accg[im][jn][half * 2 + 0];
                    float gy = accg[im][jn][half * 2 + 1];
                    float ux = accu[im][jn][half * 2 + 0];
                    float uy = accu[im][jn][half * 2 + 1];
                    float hx = (gx / (1.0f + __expf(-gx))) * ux * wt;
                    float hy = (gy / (1.0f + __expf(-gy))) * uy * wt;
                    *(__half2*)(dst + jn * 8) = __floats2half2_rn(hx, hy);
                }
            }
        }
    }
}

// ================= GEMM2 (BN=128) =================
__global__ void __launch_bounds__(THREADS)
k_gemm2(float* __restrict__ out) {
    extern __shared__ __half sm[];

    int e, nt, m_start, valid;
    if (!decode_tile(blockIdx.x, NB2, e, nt, m_start, valid)) return;

    const int tid = threadIdx.x;
    const int lane = tid & 31;
    const int wid = tid >> 5;
    const int wm = wid >> 1;
    const int wn = wid & 1;
    const int n0 = nt * 128;

    const int lr = tid >> 1;
    const int lc = (tid & 1) * 16;
    const int arc = (lr < valid) ? lr : (valid - 1);
    const __half* aptr = g_h + (size_t)(m_start + arc) * INTER + lc;
    const __half* bptr = g_w2 + (size_t)e * HIDDEN * INTER + (size_t)(n0 + lr) * INTER + lc;

    const uint32_t smb = cvta_s(sm);
    const uint32_t sAst = smb + (lr * SA + lc) * 2;
    const uint32_t sBst = smb + NSTAGE * STG_BYTES + (lr * SA + lc) * 2;
    const uint32_t aBase = smb + ((wm * 32 + (lane & 15)) * SA + (lane >> 4) * 8) * 2;
    const uint32_t bBase = smb + NSTAGE * STG_BYTES +
        ((wn * 64 + ((lane >> 4) * 8) + (lane & 7)) * SA + ((lane >> 3) & 1) * 8) * 2;

    float acc[2][8][4] = {};

    auto issue = [&](int kt) {
        if (kt < NK2) {
            const int st = kt & (NSTAGE - 1);
            const __half* a = aptr + kt * 32;
            const __half* b = bptr + kt * 32;
            cpa16(sAst + st * STG_BYTES,      a);
            cpa16(sAst + st * STG_BYTES + 16, a + 8);
            cpa16(sBst + st * STG_BYTES,      b);
            cpa16(sBst + st * STG_BYTES + 16, b + 8);
        }
        cp_commit();
    };

    issue(0); issue(1); issue(2);

    for (int kt = 0; kt < NK2; kt++) {
        cp_wait2();
        __syncthreads();
        issue(kt + 3);

        const int st = kt & (NSTAGE - 1);
        const uint32_t aS = aBase + st * STG_BYTES;
        const uint32_t bS = bBase + st * STG_BYTES;
#pragma unroll
        for (int ks = 0; ks < 2; ks++) {
            uint32_t a[2][4];
#pragma unroll
            for (int im = 0; im < 2; im++)
                ldsm4(a[im][0], a[im][1], a[im][2], a[im][3],
                      aS + ((im * 16 * SA + ks * 16) << 1));
#pragma unroll
            for (int jp = 0; jp < 4; jp++) {
                uint32_t b0, b1, b2, b3;
                ldsm4(b0, b1, b2, b3, bS + ((jp * 16 * SA + ks * 16) << 1));
#pragma unroll
                for (int im = 0; im < 2; im++) {
                    mma_f16(acc[im][jp * 2],     a[im], b0, b1);
                    mma_f16(acc[im][jp * 2 + 1], a[im], b2, b3);
                }
            }
        }
        __syncthreads();
    }

#pragma unroll
    for (int im = 0; im < 2; im++) {
#pragma unroll
        for (int half = 0; half < 2; half++) {
            const int r = wm * 32 + im * 16 + half * 8 + (lane >> 2);
            if (r < valid) {
                const int tok = g_perm[m_start + r];
                float* dst = out + (size_t)tok * HIDDEN + n0 + wn * 64 + (lane & 3) * 2;
#pragma unroll
                for (int jn = 0; jn < 8; jn++) {
                    float2 v;
                    v.x = acc[im][jn][half * 2 + 0];
                    v.y = acc[im][jn][half * 2 + 1];
                    *(float2*)(dst + jn * 8) = v;
                }
            }
        }
    }
}

// -------- launch --------
extern "C" void kernel_launch(void* const* d_in, const int* in_sizes, int n_in,
                              void* d_out, int out_size) {
    const float* tokens = (const float*)d_in[0];
    const int*   ids    = (const int*)d_in[1];
    const float* wts    = (const float*)d_in[2];
    const float* gu     = (const float*)d_in[3];
    const float* down   = (const float*)d_in[4];
    float* out = (float*)d_out;

    __half* w1p; cudaGetSymbolAddress((void**)&w1p, g_w1);
    __half* w2p; cudaGetSymbolAddress((void**)&w2p, g_w2);

    cudaFuncSetAttribute(k_gemm1, cudaFuncAttributeMaxDynamicSharedMemorySize, SMEM_BYTES);
    cudaFuncSetAttribute(k_gemm2, cudaFuncAttributeMaxDynamicSharedMemorySize, SMEM_BYTES);

    const int n8_w1 = NUM_EXPERTS * 2 * INTER * HIDDEN / 8;
    const int n8_w2 = NUM_EXPERTS * HIDDEN * INTER / 8;

    k_router<<<1, THREADS>>>(ids);
    k_cvt<<<(n8_w1 + 255) / 256, 256>>>(gu, w1p, n8_w1);
    k_cvt<<<(n8_w2 + 255) / 256, 256>>>(down, w2p, n8_w2);
    k_gather<<<NTOK, THREADS>>>(tokens);

    k_gemm1<<<MAX_MTILES * NB1, THREADS, SMEM_BYTES>>>(wts);
    k_gemm2<<<MAX_MTILES * NB2, THREADS, SMEM_BYTES>>>(out);
}

// round 7
// speedup vs baseline: 2.4118x; 1.0192x over previous
#include <cuda_runtime.h>
#include <cuda_fp16.h>
#include <stdint.h>

#define NUM_EXPERTS 8
#define HIDDEN 2048
#define INTER 1408
#define NTOK 8192

#define BM 128
#define THREADS 256
#define MAX_MTILES (NTOK/BM + NUM_EXPERTS - 1)   // 71
#define NB1 (INTER/64)     // 22
#define NB2 (HIDDEN/128)   // 16
#define NK1 (HIDDEN/32)    // 64
#define NK2 (INTER/32)     // 44
#define SA 40              // smem row stride (halfs), conflict-free ldsm

#define STG (BM*SA)
#define STG_BYTES (STG*2)
#define NSTAGE 4
#define SMEM_BYTES (2*NSTAGE*STG_BYTES)   // 81920

// -------- device scratch --------
__device__ int g_offsets[NUM_EXPERTS + 1];
__device__ int g_mtoff[NUM_EXPERTS + 1];
__device__ int g_perm[NTOK];
__device__ __half g_w1[(size_t)NUM_EXPERTS * 2 * INTER * HIDDEN];
__device__ __half g_w2[(size_t)NUM_EXPERTS * HIDDEN * INTER];
__device__ __half g_x[(size_t)NTOK * HIDDEN];
__device__ __half g_h[(size_t)NTOK * INTER];

// -------- helpers --------
__device__ __forceinline__ uint32_t cvta_s(const void* p) {
    return (uint32_t)__cvta_generic_to_shared(p);
}
__device__ __forceinline__ void ldsm4(uint32_t& r0, uint32_t& r1,
                                      uint32_t& r2, uint32_t& r3, uint32_t addr) {
    asm volatile("ldmatrix.sync.aligned.m8n8.x4.shared.b16 {%0,%1,%2,%3},[%4];"
                 : "=r"(r0), "=r"(r1), "=r"(r2), "=r"(r3) : "r"(addr));
}
__device__ __forceinline__ void mma_f16(float c[4], const uint32_t a[4],
                                        uint32_t b0, uint32_t b1) {
    asm volatile(
        "mma.sync.aligned.m16n8k16.row.col.f32.f16.f16.f32 "
        "{%0,%1,%2,%3},{%4,%5,%6,%7},{%8,%9},{%0,%1,%2,%3};\n"
        : "+f"(c[0]), "+f"(c[1]), "+f"(c[2]), "+f"(c[3])
        : "r"(a[0]), "r"(a[1]), "r"(a[2]), "r"(a[3]), "r"(b0), "r"(b1));
}
__device__ __forceinline__ void cpa16(uint32_t s, const void* g) {
    asm volatile("cp.async.cg.shared.global [%0], [%1], 16;\n" :: "r"(s), "l"(g));
}
__device__ __forceinline__ void cp_commit() {
    asm volatile("cp.async.commit_group;\n" ::: "memory");
}
__device__ __forceinline__ void cp_wait2() {
    asm volatile("cp.async.wait_group 2;\n" ::: "memory");
}
__device__ __forceinline__ uint32_t pack2(float x, float y) {
    __half2 h = __floats2half2_rn(x, y);
    return *(uint32_t*)&h;
}
__device__ __forceinline__ uint4 pack8(float4 a, float4 b) {
    uint4 v;
    v.x = pack2(a.x, a.y); v.y = pack2(a.z, a.w);
    v.z = pack2(b.x, b.y); v.w = pack2(b.z, b.w);
    return v;
}

// -------- router --------
__global__ void k_router(const int* __restrict__ ids) {
    __shared__ int sc[NUM_EXPERTS];
    __shared__ int sb[NUM_EXPERTS];
    int t = threadIdx.x;
    if (t < NUM_EXPERTS) sc[t] = 0;
    __syncthreads();
    for (int i = t; i < NTOK; i += THREADS) atomicAdd(&sc[ids[i]], 1);
    __syncthreads();
    if (t == 0) {
        int off = 0, moff = 0;
        for (int e = 0; e < NUM_EXPERTS; e++) {
            g_offsets[e] = off; sb[e] = off; g_mtoff[e] = moff;
            off  += sc[e];
            moff += (sc[e] + BM - 1) / BM;
        }
        g_offsets[NUM_EXPERTS] = off;
        g_mtoff[NUM_EXPERTS]   = moff;
    }
    __syncthreads();
    if (t < NUM_EXPERTS) sc[t] = 0;
    __syncthreads();
    for (int i = t; i < NTOK; i += THREADS) {
        int e = ids[i];
        g_perm[sb[e] + atomicAdd(&sc[e], 1)] = i;
    }
}

// -------- pre-convert both weights fp32 -> fp16 (one kernel, grid-stride, 32B/thread) --------
__global__ void k_cvt_all(const float* __restrict__ w1, const float* __restrict__ w2) {
    const long n16_w1 = (long)NUM_EXPERTS * 2 * INTER * HIDDEN / 16;
    const long n16_w2 = (long)NUM_EXPERTS * HIDDEN * INTER / 16;
    const long total = n16_w1 + n16_w2;
    __half* w1d = g_w1;
    __half* w2d = g_w2;
    long stride = (long)gridDim.x * blockDim.x;
    for (long i = (long)blockIdx.x * blockDim.x + threadIdx.x; i < total; i += stride) {
        const float* src; __half* dst; long j;
        if (i < n16_w1) { src = w1; dst = w1d; j = i; }
        else            { src = w2; dst = w2d; j = i - n16_w1; }
        const float4* s = (const float4*)src + 4 * j;
        float4 a = s[0], b = s[1], c = s[2], d = s[3];
        uint4* o = (uint4*)dst + 2 * j;
        o[0] = pack8(a, b);
        o[1] = pack8(c, d);
    }
}

// -------- gather permuted fp16 tokens --------
__global__ void k_gather(const float* __restrict__ tokens) {
    const int s = blockIdx.x;
    const int tok = g_perm[s];
    const float4* src = (const float4*)(tokens + (size_t)tok * HIDDEN);
    uint4* dst = (uint4*)(g_x + (size_t)s * HIDDEN);
    for (int i = threadIdx.x; i < HIDDEN / 8; i += THREADS)
        dst[i] = pack8(src[2 * i], src[2 * i + 1]);
}

__device__ __forceinline__ bool decode_tile(int bx, int NB,
        int& e, int& nt, int& m_start, int& valid) {
    int total = g_mtoff[NUM_EXPERTS] * NB;
    if (bx >= total) return false;
    e = 0;
    while (bx >= g_mtoff[e + 1] * NB) e++;
    int local = bx - g_mtoff[e] * NB;
    int mt = g_mtoff[e + 1] - g_mtoff[e];
    nt = local / mt;
    int ml = local % mt;
    m_start = g_offsets[e] + ml * BM;
    valid = g_offsets[e + 1] - m_start;
    if (valid > BM) valid = BM;
    return true;
}

// ================= GEMM1 =================
__global__ void __launch_bounds__(THREADS)
k_gemm1(const float* __restrict__ wts) {
    extern __shared__ __half sm[];

    int e, nt, m_start, valid;
    if (!decode_tile(blockIdx.x, NB1, e, nt, m_start, valid)) return;

    const int tid = threadIdx.x;
    const int lane = tid & 31;
    const int wid = tid >> 5;
    const int wm = wid >> 1;
    const int wn = wid & 1;
    const int n0 = nt * 64;

    const int lr = tid >> 1;
    const int lc = (tid & 1) * 16;
    const int arc = (lr < valid) ? lr : (valid - 1);
    const __half* aptr = g_x + (size_t)(m_start + arc) * HIDDEN + lc;
    const int brow = (lr < 64) ? (n0 + lr) : (INTER + n0 + lr - 64);
    const __half* bptr = g_w1 + (size_t)e * 2 * INTER * HIDDEN + (size_t)brow * HIDDEN + lc;

    const uint32_t smb = cvta_s(sm);
    const uint32_t sAst = smb + (lr * SA + lc) * 2;
    const uint32_t sBst = smb + NSTAGE * STG_BYTES + (lr * SA + lc) * 2;
    const uint32_t aBase = smb + ((wm * 32 + (lane & 15)) * SA + (lane >> 4) * 8) * 2;
    const uint32_t bBase = smb + NSTAGE * STG_BYTES +
        ((wn * 32 + ((lane >> 4) * 8) + (lane & 7)) * SA + ((lane >> 3) & 1) * 8) * 2;

    float accg[2][4][4] = {};
    float accu[2][4][4] = {};

    auto issue = [&](int kt) {
        if (kt < NK1) {
            const int st = kt & (NSTAGE - 1);
            const __half* a = aptr + kt * 32;
            const __half* b = bptr + kt * 32;
            cpa16(sAst + st * STG_BYTES,      a);
            cpa16(sAst + st * STG_BYTES + 16, a + 8);
            cpa16(sBst + st * STG_BYTES,      b);
            cpa16(sBst + st * STG_BYTES + 16, b + 8);
        }
        cp_commit();
    };

    issue(0); issue(1); issue(2);

    for (int kt = 0; kt < NK1; kt++) {
        cp_wait2();
        __syncthreads();        // single barrier per k-tile
        issue(kt + 3);

        const int st = kt & (NSTAGE - 1);
        const uint32_t aS = aBase + st * STG_BYTES;
        const uint32_t bS = bBase + st * STG_BYTES;
#pragma unroll
        for (int ks = 0; ks < 2; ks++) {
            uint32_t a[2][4];
#pragma unroll
            for (int im = 0; im < 2; im++)
                ldsm4(a[im][0], a[im][1], a[im][2], a[im][3],
                      aS + ((im * 16 * SA + ks * 16) << 1));
#pragma unroll
            for (int jp = 0; jp < 2; jp++) {
                uint32_t g0, g1, g2, g3, u0, u1, u2, u3;
                ldsm4(g0, g1, g2, g3, bS + ((jp * 16 * SA + ks * 16) << 1));
                ldsm4(u0, u1, u2, u3, bS + (((64 + jp * 16) * SA + ks * 16) << 1));
#pragma unroll
                for (int im = 0; im < 2; im++) {
                    mma_f16(accg[im][jp * 2],     a[im], g0, g1);
                    mma_f16(accg[im][jp * 2 + 1], a[im], g2, g3);
                    mma_f16(accu[im][jp * 2],     a[im], u0, u1);
                    mma_f16(accu[im][jp * 2 + 1], a[im], u2, u3);
                }
            }
        }
    }

    // epilogue: silu(g)*u*wt -> g_h (fp16)
#pragma unroll
    for (int im = 0; im < 2; im++) {
#pragma unroll
        for (int half = 0; half < 2; half++) {
            const int r = wm * 32 + im * 16 + half * 8 + (lane >> 2);
            if (r < valid) {
                const int s = m_start + r;
                const float wt = wts[g_perm[s]];
                __half* dst = g_h + (size_t)s * INTER + n0 + wn * 32 + (lane & 3) * 2;
#pragma unroll
                for (int jn = 0; jn < 4; jn++) {
                    float gx = accg[im][jn][half * 2 + 0];
                    float gy = accg[im][jn][half * 2 + 1];
                    float ux = accu[im][jn][half * 2 + 0];
                    float uy = accu[im][jn][half * 2 + 1];
                    float hx = (gx / (1.0f + __expf(-gx))) * ux * wt;
                    float hy = (gy / (1.0f + __expf(-gy))) * uy * wt;
                    *(__half2*)(dst + jn * 8) = __floats2half2_rn(hx, hy);
                }
            }
        }
    }
}

// ================= GEMM2 (BN=128) =================
__global__ void __launch_bounds__(THREADS)
k_gemm2(float* __restrict__ out) {
    extern __shared__ __half sm[];

    int e, nt, m_start, valid;
    if (!decode_tile(blockIdx.x, NB2, e, nt, m_start, valid)) return;

    const int tid = threadIdx.x;
    const int lane = tid & 31;
    const int wid = tid >> 5;
    const int wm = wid >> 1;
    const int wn = wid & 1;
    const int n0 = nt * 128;

    const int lr = tid >> 1;
    const int lc = (tid & 1) * 16;
    const int arc = (lr < valid) ? lr : (valid - 1);
    const __half* aptr = g_h + (size_t)(m_start + arc) * INTER + lc;
    const __half* bptr = g_w2 + (size_t)e * HIDDEN * INTER + (size_t)(n0 + lr) * INTER + lc;

    const uint32_t smb = cvta_s(sm);
    const uint32_t sAst = smb + (lr * SA + lc) * 2;
    const uint32_t sBst = smb + NSTAGE * STG_BYTES + (lr * SA + lc) * 2;
    const uint32_t aBase = smb + ((wm * 32 + (lane & 15)) * SA + (lane >> 4) * 8) * 2;
    const uint32_t bBase = smb + NSTAGE * STG_BYTES +
        ((wn * 64 + ((lane >> 4) * 8) + (lane & 7)) * SA + ((lane >> 3) & 1) * 8) * 2;

    float acc[2][8][4] = {};

    auto issue = [&](int kt) {
        if (kt < NK2) {
            const int st = kt & (NSTAGE - 1);
            const __half* a = aptr + kt * 32;
            const __half* b = bptr + kt * 32;
            cpa16(sAst + st * STG_BYTES,      a);
            cpa16(sAst + st * STG_BYTES + 16, a + 8);
            cpa16(sBst + st * STG_BYTES,      b);
            cpa16(sBst + st * STG_BYTES + 16, b + 8);
        }
        cp_commit();
    };

    issue(0); issue(1); issue(2);

    for (int kt = 0; kt < NK2; kt++) {
        cp_wait2();
        __syncthreads();        // single barrier per k-tile
        issue(kt + 3);

        const int st = kt & (NSTAGE - 1);
        const uint32_t aS = aBase + st * STG_BYTES;
        const uint32_t bS = bBase + st * STG_BYTES;
#pragma unroll
        for (int ks = 0; ks < 2; ks++) {
            uint32_t a[2][4];
#pragma unroll
            for (int im = 0; im < 2; im++)
                ldsm4(a[im][0], a[im][1], a[im][2], a[im][3],
                      aS + ((im * 16 * SA + ks * 16) << 1));
#pragma unroll
            for (int jp = 0; jp < 4; jp++) {
                uint32_t b0, b1, b2, b3;
                ldsm4(b0, b1, b2, b3, bS + ((jp * 16 * SA + ks * 16) << 1));
#pragma unroll
                for (int im = 0; im < 2; im++) {
                    mma_f16(acc[im][jp * 2],     a[im], b0, b1);
                    mma_f16(acc[im][jp * 2 + 1], a[im], b2, b3);
                }
            }
        }
    }

#pragma unroll
    for (int im = 0; im < 2; im++) {
#pragma unroll
        for (int half = 0; half < 2; half++) {
            const int r = wm * 32 + im * 16 + half * 8 + (lane >> 2);
            if (r < valid) {
                const int tok = g_perm[m_start + r];
                float* dst = out + (size_t)tok * HIDDEN + n0 + wn * 64 + (lane & 3) * 2;
#pragma unroll
                for (int jn = 0; jn < 8; jn++) {
                    float2 v;
                    v.x = acc[im][jn][half * 2 + 0];
                    v.y = acc[im][jn][half * 2 + 1];
                    *(float2*)(dst + jn * 8) = v;
                }
            }
        }
    }
}

// -------- launch --------
extern "C" void kernel_launch(void* const* d_in, const int* in_sizes, int n_in,
                              void* d_out, int out_size) {
    const float* tokens = (const float*)d_in[0];
    const int*   ids    = (const int*)d_in[1];
    const float* wts    = (const float*)d_in[2];
    const float* gu     = (const float*)d_in[3];
    const float* down   = (const float*)d_in[4];
    float* out = (float*)d_out;

    cudaFuncSetAttribute(k_gemm1, cudaFuncAttributeMaxDynamicSharedMemorySize, SMEM_BYTES);
    cudaFuncSetAttribute(k_gemm2, cudaFuncAttributeMaxDynamicSharedMemorySize, SMEM_BYTES);

    k_router<<<1, THREADS>>>(ids);
    k_cvt_all<<<148 * 16, 256>>>(gu, down);
    k_gather<<<NTOK, THREADS>>>(tokens);

    k_gemm1<<<MAX_MTILES * NB1, THREADS, SMEM_BYTES>>>(wts);
    k_gemm2<<<MAX_MTILES * NB2, THREADS, SMEM_BYTES>>>(out);
}